// round 1
// baseline (speedup 1.0000x reference)
#include <cuda_runtime.h>
#include <math.h>

#define NPTS 40000
#define KNN  16
#define CCH  128
// 1/sqrt(1 + 1e-5)  (BatchNorm eval with running_var = 1)
#define RSQ  0.9999950000374997f

// ---------------- scratch (no allocations allowed) ----------------
static __device__ float g_h  [NPTS * CCH];   // main residual stream
static __device__ float g_xp [NPTS * CCH];   // spse output / lfp proj output
static __device__ float g_tmp[NPTS * 512];   // MLP hidden (max width 512)

__device__ __forceinline__ float gelu_tanh(float x) {
    // jax.nn.gelu(approximate=True)
    float x3 = x * x * x;
    return 0.5f * x * (1.0f + tanhf(0.7978845608028654f * (x + 0.044715f * x3)));
}

// ---------------- spse + BN0 ----------------
// One block per point, one thread per channel.
__global__ void __launch_bounds__(128) spse_kernel(
    const float* __restrict__ x, const float* __restrict__ xyz,
    const int* __restrict__ knn,
    const float* __restrict__ spse_m, const float* __restrict__ spse_c,
    const float* __restrict__ spse_h,
    const float* __restrict__ g0, const float* __restrict__ b0,
    float* __restrict__ out)
{
    int n = blockIdx.x;
    int c = threadIdx.x;

    // dirs[j][d][c] = spse_m[(j*4+d)*C + c]; rel4[3] == 0 so d=3 unused
    float M0x = spse_m[0 * CCH + c], M0y = spse_m[1 * CCH + c], M0z = spse_m[2 * CCH + c];
    float M1x = spse_m[4 * CCH + c], M1y = spse_m[5 * CCH + c], M1z = spse_m[6 * CCH + c];
    float M2x = spse_m[8 * CCH + c], M2y = spse_m[9 * CCH + c], M2z = spse_m[10 * CCH + c];
    float c0 = spse_c[0 * CCH + c]; c0 *= c0;
    float c1 = spse_c[1 * CCH + c]; c1 *= c1;
    float c2 = spse_c[2 * CCH + c]; c2 *= c2;
    float h2 = spse_h[c]; h2 *= h2;

    float px = xyz[n * 3 + 0], py = xyz[n * 3 + 1], pz = xyz[n * 3 + 2];
    float f0 = x[n * 4 + 0], f1 = x[n * 4 + 1], f2 = x[n * 4 + 2], f3 = x[n * 4 + 3];

    float e = 0.0f;
    #pragma unroll
    for (int k = 0; k < KNN; ++k) {
        int nb = knn[n * KNN + k];                 // uniform across block -> broadcast
        float dx = xyz[nb * 3 + 0] - px;
        float dy = xyz[nb * 3 + 1] - py;
        float dz = xyz[nb * 3 + 2] - pz;
        float r0 = x[nb * 4 + 0] - f0;
        float r1 = x[nb * 4 + 1] - f1;
        float r2 = x[nb * 4 + 2] - f2;
        float r3 = x[nb * 4 + 3] - f3;
        float d0 = dx * M0x + dy * M0y + dz * M0z;
        float d1 = dx * M1x + dy * M1y + dz * M1z;
        float d2 = dx * M2x + dy * M2y + dz * M2z;
        e += d0 * d0 + d1 * d1 + d2 * d2;
        e += r0 * r0 * c0 + r1 * r1 * c1 + r2 * r2 * c2 + r3 * r3 * h2;
    }
    float r = sqrtf(e * (1.0f / (float)KNN));
    out[n * CCH + c] = r * g0[c] * RSQ + b0[c];
}

// ---------------- LFP gather + PE + max + BN + residual ----------------
// h is read AND written (residual in-place). One block per point.
__global__ void __launch_bounds__(128) lfp_kernel(
    const float* __restrict__ xp, const float* __restrict__ xyz,
    const int* __restrict__ knn,
    const float* __restrict__ coor,  // (3, 32)
    const float* __restrict__ scale, // (32,)
    const float* __restrict__ g, const float* __restrict__ b,
    float* h)
{
    int n = blockIdx.x;
    int c = threadIdx.x;
    int d = c >> 2;
    float s2 = scale[d]; s2 *= s2;
    float k0 = coor[0 * 32 + d] * s2;
    float k1 = coor[1 * 32 + d] * s2;
    float k2 = coor[2 * 32 + d] * s2;

    float px = xyz[n * 3 + 0], py = xyz[n * 3 + 1], pz = xyz[n * 3 + 2];

    float m = -INFINITY;
    #pragma unroll
    for (int k = 0; k < KNN; ++k) {
        int nb = knn[n * KNN + k];                 // uniform -> broadcast
        float pe = (xyz[nb * 3 + 0] - px) * k0
                 + (xyz[nb * 3 + 1] - py) * k1
                 + (xyz[nb * 3 + 2] - pz) * k2;
        float v = xp[nb * CCH + c] + pe;           // coalesced 512B row gather (L2 hit)
        m = fmaxf(m, v);
    }
    h[n * CCH + c] = h[n * CCH + c] + (m * g[c] * RSQ + b[c]);
}

// ---------------- generic fp32 GEMM with fused prologue/epilogue ----------------
// C(N x M) = epilogue( prologue(A)(N x K) @ B(K x M) )
// prologue: A' = A * a_scale[k]*RSQ + a_bias[k]   (folds a BatchNorm into A)
// epilogue: +bias[col]; GELU; BN(col); +residual (residual may alias Cout)
// All dims: N = 40000 (multiple of 64), K in {128,256,512}, M in {128,256,512}.
__global__ void __launch_bounds__(256) gemm_ep(
    const float* __restrict__ A, const float* __restrict__ B, float* Cout,
    int K, int M,
    const float* __restrict__ a_scale, const float* __restrict__ a_bias,
    const float* __restrict__ bias, int act,
    const float* __restrict__ bn_g, const float* __restrict__ bn_b,
    const float* residual)
{
    __shared__ float As[16][68];   // [k][m], pad 68 -> float4-aligned rows, low conflicts
    __shared__ float Bs[16][68];   // [k][n]

    int t  = threadIdx.x;
    int bm = blockIdx.x * 64;   // along N (625 blocks)
    int bn = blockIdx.y * 64;   // along M
    int tx = t & 15, ty = t >> 4;

    int la_m = t >> 2;          // 0..63
    int la_k = (t & 3) * 4;     // 0,4,8,12
    int lb_k = t >> 4;          // 0..15
    int lb_n = (t & 15) * 4;    // 0..60

    float acc[4][4] = {};

    for (int k0 = 0; k0 < K; k0 += 16) {
        float4 av = *(const float4*)&A[(size_t)(bm + la_m) * K + k0 + la_k];
        if (a_scale) {
            av.x = av.x * a_scale[k0 + la_k + 0] * RSQ + a_bias[k0 + la_k + 0];
            av.y = av.y * a_scale[k0 + la_k + 1] * RSQ + a_bias[k0 + la_k + 1];
            av.z = av.z * a_scale[k0 + la_k + 2] * RSQ + a_bias[k0 + la_k + 2];
            av.w = av.w * a_scale[k0 + la_k + 3] * RSQ + a_bias[k0 + la_k + 3];
        }
        As[la_k + 0][la_m] = av.x;
        As[la_k + 1][la_m] = av.y;
        As[la_k + 2][la_m] = av.z;
        As[la_k + 3][la_m] = av.w;
        *(float4*)&Bs[lb_k][lb_n] = *(const float4*)&B[(size_t)(k0 + lb_k) * M + bn + lb_n];
        __syncthreads();

        #pragma unroll
        for (int kk = 0; kk < 16; ++kk) {
            float4 a = *(const float4*)&As[kk][ty * 4];
            float4 b = *(const float4*)&Bs[kk][tx * 4];
            float ar[4] = {a.x, a.y, a.z, a.w};
            float br[4] = {b.x, b.y, b.z, b.w};
            #pragma unroll
            for (int i = 0; i < 4; ++i)
                #pragma unroll
                for (int j = 0; j < 4; ++j)
                    acc[i][j] = fmaf(ar[i], br[j], acc[i][j]);
        }
        __syncthreads();
    }

    #pragma unroll
    for (int i = 0; i < 4; ++i) {
        int row = bm + ty * 4 + i;
        #pragma unroll
        for (int j = 0; j < 4; ++j) {
            int col = bn + tx * 4 + j;
            float v = acc[i][j];
            if (bias) v += bias[col];
            if (act)  v = gelu_tanh(v);
            if (bn_g) v = v * bn_g[col] * RSQ + bn_b[col];
            size_t idx = (size_t)row * M + col;
            if (residual) v += residual[idx];
            Cout[idx] = v;
        }
    }
}

// ---------------- driver ----------------
extern "C" void kernel_launch(void* const* d_in, const int* in_sizes, int n_in,
                              void* d_out, int out_size)
{
    const float* x      = (const float*)d_in[0];
    const float* xyz    = (const float*)d_in[1];
    const int*   knn    = (const int*)  d_in[2];
    const float* spse_m = (const float*)d_in[3];
    const float* spse_c = (const float*)d_in[4];
    const float* spse_h = (const float*)d_in[5];
    const float* bn0g   = (const float*)d_in[6];
    const float* bn0b   = (const float*)d_in[7];
    const float* w1     = (const float*)d_in[8];
    const float* b1     = (const float*)d_in[9];
    const float* w2     = (const float*)d_in[10];
    const float* bng    = (const float*)d_in[11];
    const float* bnb    = (const float*)d_in[12];
    const float* proj   = (const float*)d_in[13];
    const float* coor   = (const float*)d_in[14];
    const float* scl    = (const float*)d_in[15];
    const float* lbng   = (const float*)d_in[16];
    const float* lbnb   = (const float*)d_in[17];
    const float* mw1    = (const float*)d_in[18];
    const float* mb1    = (const float*)d_in[19];
    const float* mw2    = (const float*)d_in[20];
    const float* mbng   = (const float*)d_in[21];
    const float* mbnb   = (const float*)d_in[22];
    const float* pg     = (const float*)d_in[23];
    const float* pb     = (const float*)d_in[24];
    const float* pw     = (const float*)d_in[25];
    float* out = (float*)d_out;

    float *h, *xp, *tmp;
    cudaGetSymbolAddress((void**)&h,   g_h);
    cudaGetSymbolAddress((void**)&xp,  g_xp);
    cudaGetSymbolAddress((void**)&tmp, g_tmp);

    dim3 blk(256);
    dim3 g2(625, 2), g4(625, 4), g8(625, 8);

    // nbr = bn0(knn_spse4(...))
    spse_kernel<<<NPTS, 128>>>(x, xyz, knn, spse_m, spse_c, spse_h, bn0g, bn0b, xp);
    // h = bn( gelu(nbr @ w1 + b1) @ w2 )
    gemm_ep<<<g4, blk>>>(xp, w1, tmp, 128, 256, 0, 0, b1, 1, 0, 0, 0);
    gemm_ep<<<g2, blk>>>(tmp, w2, h, 256, 128, 0, 0, 0, 0, bng, bnb, 0);
    // h += mlp0(h)
    gemm_ep<<<g8, blk>>>(h, mw1, tmp, 128, 512, 0, 0, mb1, 1, 0, 0, 0);
    gemm_ep<<<g2, blk>>>(tmp, mw2, h, 512, 128, 0, 0, 0, 0, mbng, mbnb, h);

    for (int i = 0; i < 4; ++i) {
        // xp = h @ proj[i]
        gemm_ep<<<g2, blk>>>(h, proj + (size_t)i * CCH * CCH, xp, 128, 128,
                             0, 0, 0, 0, 0, 0, 0);
        // h += bn( max_k( xp[knn] + pe ) )
        lfp_kernel<<<NPTS, 128>>>(xp, xyz, knn, coor + i * 3 * 32, scl + i * 32,
                                  lbng + i * CCH, lbnb + i * CCH, h);
        if (i & 1) {
            int j = i / 2 + 1;
            gemm_ep<<<g8, blk>>>(h, mw1 + (size_t)j * CCH * 512, tmp, 128, 512,
                                 0, 0, mb1 + j * 512, 1, 0, 0, 0);
            gemm_ep<<<g2, blk>>>(tmp, mw2 + (size_t)j * 512 * CCH, h, 512, 128,
                                 0, 0, 0, 0, mbng + j * CCH, mbnb + j * CCH, h);
        }
    }
    // out = bn(h) @ post_w   (BN folded into A prologue)
    gemm_ep<<<g4, blk>>>(h, pw, out, 128, 256, pg, pb, 0, 0, 0, 0, 0);
}

// round 2
// speedup vs baseline: 1.1633x; 1.1633x over previous
#include <cuda_runtime.h>
#include <math.h>

#define NPTS 40000
#define KNN  16
#define CCH  128
// 1/sqrt(1 + 1e-5)  (BatchNorm eval with running_var = 1)
#define RSQ  0.9999950000374997f

// ---------------- scratch (no allocations allowed) ----------------
static __device__ float g_h  [NPTS * CCH];   // main residual stream
static __device__ float g_xp [NPTS * CCH];   // spse output / lfp proj output
static __device__ float g_tmp[NPTS * 512];   // MLP hidden (max width 512)

__device__ __forceinline__ float gelu_tanh(float x) {
    // jax.nn.gelu(approximate=True)
    float x3 = x * x * x;
    return 0.5f * x * (1.0f + tanhf(0.7978845608028654f * (x + 0.044715f * x3)));
}

// ---------------- spse + BN0 ----------------
__global__ void __launch_bounds__(128) spse_kernel(
    const float* __restrict__ x, const float* __restrict__ xyz,
    const int* __restrict__ knn,
    const float* __restrict__ spse_m, const float* __restrict__ spse_c,
    const float* __restrict__ spse_h,
    const float* __restrict__ g0, const float* __restrict__ b0,
    float* __restrict__ out)
{
    int n = blockIdx.x;
    int c = threadIdx.x;

    float M0x = spse_m[0 * CCH + c], M0y = spse_m[1 * CCH + c], M0z = spse_m[2 * CCH + c];
    float M1x = spse_m[4 * CCH + c], M1y = spse_m[5 * CCH + c], M1z = spse_m[6 * CCH + c];
    float M2x = spse_m[8 * CCH + c], M2y = spse_m[9 * CCH + c], M2z = spse_m[10 * CCH + c];
    float c0 = spse_c[0 * CCH + c]; c0 *= c0;
    float c1 = spse_c[1 * CCH + c]; c1 *= c1;
    float c2 = spse_c[2 * CCH + c]; c2 *= c2;
    float h2 = spse_h[c]; h2 *= h2;

    float px = xyz[n * 3 + 0], py = xyz[n * 3 + 1], pz = xyz[n * 3 + 2];
    float f0 = x[n * 4 + 0], f1 = x[n * 4 + 1], f2 = x[n * 4 + 2], f3 = x[n * 4 + 3];

    float e = 0.0f;
    #pragma unroll
    for (int k = 0; k < KNN; ++k) {
        int nb = knn[n * KNN + k];
        float dx = xyz[nb * 3 + 0] - px;
        float dy = xyz[nb * 3 + 1] - py;
        float dz = xyz[nb * 3 + 2] - pz;
        float r0 = x[nb * 4 + 0] - f0;
        float r1 = x[nb * 4 + 1] - f1;
        float r2 = x[nb * 4 + 2] - f2;
        float r3 = x[nb * 4 + 3] - f3;
        float d0 = dx * M0x + dy * M0y + dz * M0z;
        float d1 = dx * M1x + dy * M1y + dz * M1z;
        float d2 = dx * M2x + dy * M2y + dz * M2z;
        e += d0 * d0 + d1 * d1 + d2 * d2;
        e += r0 * r0 * c0 + r1 * r1 * c1 + r2 * r2 * c2 + r3 * r3 * h2;
    }
    float r = sqrtf(e * (1.0f / (float)KNN));
    out[n * CCH + c] = r * g0[c] * RSQ + b0[c];
}

// ---------------- LFP gather + PE + max + BN + residual ----------------
__global__ void __launch_bounds__(128) lfp_kernel(
    const float* __restrict__ xp, const float* __restrict__ xyz,
    const int* __restrict__ knn,
    const float* __restrict__ coor,  // (3, 32)
    const float* __restrict__ scale, // (32,)
    const float* __restrict__ g, const float* __restrict__ b,
    float* h)
{
    int n = blockIdx.x;
    int c = threadIdx.x;
    int d = c >> 2;
    float s2 = scale[d]; s2 *= s2;
    float k0 = coor[0 * 32 + d] * s2;
    float k1 = coor[1 * 32 + d] * s2;
    float k2 = coor[2 * 32 + d] * s2;

    float px = xyz[n * 3 + 0], py = xyz[n * 3 + 1], pz = xyz[n * 3 + 2];

    float m = -INFINITY;
    #pragma unroll
    for (int k = 0; k < KNN; ++k) {
        int nb = knn[n * KNN + k];
        float pe = (xyz[nb * 3 + 0] - px) * k0
                 + (xyz[nb * 3 + 1] - py) * k1
                 + (xyz[nb * 3 + 2] - pz) * k2;
        float v = xp[nb * CCH + c] + pe;
        m = fmaxf(m, v);
    }
    h[n * CCH + c] = h[n * CCH + c] + (m * g[c] * RSQ + b[c]);
}

// ---------------- TF32 tensor-core GEMM (3xTF32 compensated) ----------------
// C(R x M) = epilogue( prologue(A)(R x K) @ B(K x M) )
// BM=64 rows, BN=128 cols, BK=16, 256 threads (8 warps, 2x4), warp tile 32x32.
// Accuracy: acc += a_lo*b_hi + a_hi*b_lo + a_hi*b_hi  (~fp32 accuracy)

#define BM 64
#define BN 128
#define BK 16
#define AS_STRIDE 68    // [k][m] layout, bank = (4k+m)%32 all-distinct
#define BS_STRIDE 132   // [k][n] layout, bank = (4k+n)%32 all-distinct

__device__ __forceinline__ unsigned f2tf32(float x) {
    unsigned r;
    asm("cvt.rna.tf32.f32 %0, %1;" : "=r"(r) : "f"(x));
    return r;
}

__device__ __forceinline__ void mma884(float* c, const unsigned* a, const unsigned* b) {
    asm volatile(
        "mma.sync.aligned.m16n8k8.row.col.f32.tf32.tf32.f32 "
        "{%0,%1,%2,%3}, {%4,%5,%6,%7}, {%8,%9}, {%0,%1,%2,%3};"
        : "+f"(c[0]), "+f"(c[1]), "+f"(c[2]), "+f"(c[3])
        : "r"(a[0]), "r"(a[1]), "r"(a[2]), "r"(a[3]), "r"(b[0]), "r"(b[1]));
}

__global__ void __launch_bounds__(256) gemm_tc(
    const float* __restrict__ A, const float* __restrict__ B, float* Cout,
    int K, int M,
    const float* __restrict__ a_scale, const float* __restrict__ a_bias,
    const float* __restrict__ bias, int act,
    const float* __restrict__ bn_g, const float* __restrict__ bn_b,
    const float* residual)
{
    __shared__ float As[2][BK][AS_STRIDE];
    __shared__ float Bs[2][BK][BS_STRIDE];

    int t = threadIdx.x;
    int lane = t & 31, wid = t >> 5;
    int wm = wid >> 2;      // 0..1  -> rows wm*32
    int wn = wid & 3;       // 0..3  -> cols wn*32
    int bm = blockIdx.x * BM;
    int bn = blockIdx.y * BN;
    int gid = lane >> 2;    // groupID 0..7
    int tig = lane & 3;     // thread-in-group 0..3

    // A load mapping: thread -> (row=t/4, k4=(t%4)*4), one float4
    int a_row = t >> 2;
    int a_k4  = (t & 3) << 2;
    // B load mapping: 2 float4 per thread: v = t + 256*s -> k=v/32, n4=(v%32)*4
    int b_k0 = t >> 5;
    int b_n4 = (t & 31) << 2;

    float acc[2][4][4] = {};

    int niter = K / BK;

    // --- preload iter 0 ---
    {
        float4 av = *(const float4*)&A[(size_t)(bm + a_row) * K + a_k4];
        if (a_scale) {
            av.x = av.x * a_scale[a_k4 + 0] * RSQ + a_bias[a_k4 + 0];
            av.y = av.y * a_scale[a_k4 + 1] * RSQ + a_bias[a_k4 + 1];
            av.z = av.z * a_scale[a_k4 + 2] * RSQ + a_bias[a_k4 + 2];
            av.w = av.w * a_scale[a_k4 + 3] * RSQ + a_bias[a_k4 + 3];
        }
        As[0][a_k4 + 0][a_row] = av.x;
        As[0][a_k4 + 1][a_row] = av.y;
        As[0][a_k4 + 2][a_row] = av.z;
        As[0][a_k4 + 3][a_row] = av.w;
        float4 bv0 = *(const float4*)&B[(size_t)(b_k0) * M + bn + b_n4];
        float4 bv1 = *(const float4*)&B[(size_t)(b_k0 + 8) * M + bn + b_n4];
        *(float4*)&Bs[0][b_k0][b_n4] = bv0;
        *(float4*)&Bs[0][b_k0 + 8][b_n4] = bv1;
    }
    __syncthreads();

    for (int it = 0; it < niter; ++it) {
        int cur = it & 1;
        float4 av, bv0, bv1;
        if (it + 1 < niter) {
            int k0 = (it + 1) * BK;
            av = *(const float4*)&A[(size_t)(bm + a_row) * K + k0 + a_k4];
            if (a_scale) {
                av.x = av.x * a_scale[k0 + a_k4 + 0] * RSQ + a_bias[k0 + a_k4 + 0];
                av.y = av.y * a_scale[k0 + a_k4 + 1] * RSQ + a_bias[k0 + a_k4 + 1];
                av.z = av.z * a_scale[k0 + a_k4 + 2] * RSQ + a_bias[k0 + a_k4 + 2];
                av.w = av.w * a_scale[k0 + a_k4 + 3] * RSQ + a_bias[k0 + a_k4 + 3];
            }
            bv0 = *(const float4*)&B[(size_t)(k0 + b_k0) * M + bn + b_n4];
            bv1 = *(const float4*)&B[(size_t)(k0 + b_k0 + 8) * M + bn + b_n4];
        }

        // compute on smem[cur]
        #pragma unroll
        for (int ks = 0; ks < BK; ks += 8) {
            unsigned ah[2][4], al[2][4], bh[4][2], bl[4][2];
            #pragma unroll
            for (int mt = 0; mt < 2; ++mt) {
                int m0 = wm * 32 + mt * 16 + gid;
                float f0 = As[cur][ks + tig    ][m0];
                float f1 = As[cur][ks + tig    ][m0 + 8];
                float f2 = As[cur][ks + tig + 4][m0];
                float f3 = As[cur][ks + tig + 4][m0 + 8];
                ah[mt][0] = f2tf32(f0); al[mt][0] = f2tf32(f0 - __uint_as_float(ah[mt][0]));
                ah[mt][1] = f2tf32(f1); al[mt][1] = f2tf32(f1 - __uint_as_float(ah[mt][1]));
                ah[mt][2] = f2tf32(f2); al[mt][2] = f2tf32(f2 - __uint_as_float(ah[mt][2]));
                ah[mt][3] = f2tf32(f3); al[mt][3] = f2tf32(f3 - __uint_as_float(ah[mt][3]));
            }
            #pragma unroll
            for (int nt = 0; nt < 4; ++nt) {
                int n0 = wn * 32 + nt * 8 + gid;
                float g0 = Bs[cur][ks + tig    ][n0];
                float g1 = Bs[cur][ks + tig + 4][n0];
                bh[nt][0] = f2tf32(g0); bl[nt][0] = f2tf32(g0 - __uint_as_float(bh[nt][0]));
                bh[nt][1] = f2tf32(g1); bl[nt][1] = f2tf32(g1 - __uint_as_float(bh[nt][1]));
            }
            #pragma unroll
            for (int mt = 0; mt < 2; ++mt)
                #pragma unroll
                for (int nt = 0; nt < 4; ++nt) {
                    mma884(acc[mt][nt], al[mt], bh[nt]);
                    mma884(acc[mt][nt], ah[mt], bl[nt]);
                    mma884(acc[mt][nt], ah[mt], bh[nt]);
                }
        }

        if (it + 1 < niter) {
            int nxt = cur ^ 1;
            As[nxt][a_k4 + 0][a_row] = av.x;
            As[nxt][a_k4 + 1][a_row] = av.y;
            As[nxt][a_k4 + 2][a_row] = av.z;
            As[nxt][a_k4 + 3][a_row] = av.w;
            *(float4*)&Bs[nxt][b_k0][b_n4] = bv0;
            *(float4*)&Bs[nxt][b_k0 + 8][b_n4] = bv1;
            __syncthreads();
        }
    }

    // --- epilogue ---
    #pragma unroll
    for (int mt = 0; mt < 2; ++mt) {
        #pragma unroll
        for (int nt = 0; nt < 4; ++nt) {
            int c0 = bn + wn * 32 + nt * 8 + tig * 2;
            #pragma unroll
            for (int half = 0; half < 2; ++half) {
                int row = bm + wm * 32 + mt * 16 + gid + half * 8;
                float v0 = acc[mt][nt][half * 2 + 0];
                float v1 = acc[mt][nt][half * 2 + 1];
                if (bias) { v0 += bias[c0]; v1 += bias[c0 + 1]; }
                if (act)  { v0 = gelu_tanh(v0); v1 = gelu_tanh(v1); }
                if (bn_g) {
                    v0 = v0 * bn_g[c0] * RSQ + bn_b[c0];
                    v1 = v1 * bn_g[c0 + 1] * RSQ + bn_b[c0 + 1];
                }
                size_t idx = (size_t)row * M + c0;
                if (residual) { v0 += residual[idx]; v1 += residual[idx + 1]; }
                *(float2*)&Cout[idx] = make_float2(v0, v1);
            }
        }
    }
}

// ---------------- driver ----------------
extern "C" void kernel_launch(void* const* d_in, const int* in_sizes, int n_in,
                              void* d_out, int out_size)
{
    const float* x      = (const float*)d_in[0];
    const float* xyz    = (const float*)d_in[1];
    const int*   knn    = (const int*)  d_in[2];
    const float* spse_m = (const float*)d_in[3];
    const float* spse_c = (const float*)d_in[4];
    const float* spse_h = (const float*)d_in[5];
    const float* bn0g   = (const float*)d_in[6];
    const float* bn0b   = (const float*)d_in[7];
    const float* w1     = (const float*)d_in[8];
    const float* b1     = (const float*)d_in[9];
    const float* w2     = (const float*)d_in[10];
    const float* bng    = (const float*)d_in[11];
    const float* bnb    = (const float*)d_in[12];
    const float* proj   = (const float*)d_in[13];
    const float* coor   = (const float*)d_in[14];
    const float* scl    = (const float*)d_in[15];
    const float* lbng   = (const float*)d_in[16];
    const float* lbnb   = (const float*)d_in[17];
    const float* mw1    = (const float*)d_in[18];
    const float* mb1    = (const float*)d_in[19];
    const float* mw2    = (const float*)d_in[20];
    const float* mbng   = (const float*)d_in[21];
    const float* mbnb   = (const float*)d_in[22];
    const float* pg     = (const float*)d_in[23];
    const float* pb     = (const float*)d_in[24];
    const float* pw     = (const float*)d_in[25];
    float* out = (float*)d_out;

    float *h, *xp, *tmp;
    cudaGetSymbolAddress((void**)&h,   g_h);
    cudaGetSymbolAddress((void**)&xp,  g_xp);
    cudaGetSymbolAddress((void**)&tmp, g_tmp);

    dim3 blk(256);
    dim3 gM128(625, 1), gM256(625, 2), gM512(625, 4);

    // nbr = bn0(knn_spse4(...))
    spse_kernel<<<NPTS, 128>>>(x, xyz, knn, spse_m, spse_c, spse_h, bn0g, bn0b, xp);
    // h = bn( gelu(nbr @ w1 + b1) @ w2 )
    gemm_tc<<<gM256, blk>>>(xp, w1, tmp, 128, 256, 0, 0, b1, 1, 0, 0, 0);
    gemm_tc<<<gM128, blk>>>(tmp, w2, h, 256, 128, 0, 0, 0, 0, bng, bnb, 0);
    // h += mlp0(h)
    gemm_tc<<<gM512, blk>>>(h, mw1, tmp, 128, 512, 0, 0, mb1, 1, 0, 0, 0);
    gemm_tc<<<gM128, blk>>>(tmp, mw2, h, 512, 128, 0, 0, 0, 0, mbng, mbnb, h);

    for (int i = 0; i < 4; ++i) {
        gemm_tc<<<gM128, blk>>>(h, proj + (size_t)i * CCH * CCH, xp, 128, 128,
                                0, 0, 0, 0, 0, 0, 0);
        lfp_kernel<<<NPTS, 128>>>(xp, xyz, knn, coor + i * 3 * 32, scl + i * 32,
                                  lbng + i * CCH, lbnb + i * CCH, h);
        if (i & 1) {
            int j = i / 2 + 1;
            gemm_tc<<<gM512, blk>>>(h, mw1 + (size_t)j * CCH * 512, tmp, 128, 512,
                                    0, 0, mb1 + j * 512, 1, 0, 0, 0);
            gemm_tc<<<gM128, blk>>>(tmp, mw2 + (size_t)j * 512 * CCH, h, 512, 128,
                                    0, 0, 0, 0, mbng + j * CCH, mbnb + j * CCH, h);
        }
    }
    // out = bn(h) @ post_w   (BN folded into A prologue)
    gemm_tc<<<gM256, blk>>>(h, pw, out, 128, 256, pg, pb, 0, 0, 0, 0, 0);
}